// round 1
// baseline (speedup 1.0000x reference)
#include <cuda_runtime.h>

#define BATCH   8
#define NPTS    4096
#define THREADS 128
#define CHUNKS  (NPTS / THREADS)   // 32 chunks of query points per batch
#define TILE    2048               // candidate tile in smem (32 KB as float4)

__global__ void zero_kernel(float* out) {
    if (threadIdx.x == 0) out[0] = 0.0f;
}

__global__ __launch_bounds__(THREADS)
void chamfer_kernel(const float* __restrict__ pred,
                    const float* __restrict__ target,
                    float* __restrict__ out)
{
    // smem: candidate points as (t^2, -2x, -2y, -2z)
    __shared__ float4 sm[TILE];
    __shared__ float  wsum[THREADS / 32];

    int bid = blockIdx.x;
    int dir = (bid >= BATCH * CHUNKS) ? 1 : 0;
    if (dir) bid -= BATCH * CHUNKS;
    int b     = bid / CHUNKS;
    int chunk = bid % CHUNKS;

    // dir 0: query = pred, candidates = target (min_pred_to_target)
    // dir 1: query = target, candidates = pred (min_target_to_pred)
    const float* Q = dir ? target : pred;
    const float* C = dir ? pred   : target;

    // this thread's query point
    int i = chunk * THREADS + threadIdx.x;
    const float* qp = Q + ((size_t)b * NPTS + i) * 3;
    float px = qp[0], py = qp[1], pz = qp[2];
    float p2 = px * px + py * py + pz * pz;

    const float* cbase = C + (size_t)b * NPTS * 3;

    float m0 = 3.0e38f, m1 = 3.0e38f, m2 = 3.0e38f, m3 = 3.0e38f;

    for (int t0 = 0; t0 < NPTS; t0 += TILE) {
        __syncthreads();   // previous tile fully consumed before overwrite
        // cooperative load + transform of TILE candidates
        for (int j = threadIdx.x; j < TILE; j += THREADS) {
            const float* cp = cbase + (size_t)(t0 + j) * 3;
            float x = cp[0], y = cp[1], z = cp[2];
            sm[j] = make_float4(x * x + y * y + z * z,
                                -2.0f * x, -2.0f * y, -2.0f * z);
        }
        __syncthreads();

        // min over tile: val = t2 - 2 p.t  (3 FFMA + 1 min per candidate)
        #pragma unroll 4
        for (int j = 0; j < TILE; j += 4) {
            float4 c0 = sm[j + 0];
            float4 c1 = sm[j + 1];
            float4 c2 = sm[j + 2];
            float4 c3 = sm[j + 3];
            float v0 = fmaf(c0.y, px, fmaf(c0.z, py, fmaf(c0.w, pz, c0.x)));
            float v1 = fmaf(c1.y, px, fmaf(c1.z, py, fmaf(c1.w, pz, c1.x)));
            float v2 = fmaf(c2.y, px, fmaf(c2.z, py, fmaf(c2.w, pz, c2.x)));
            float v3 = fmaf(c3.y, px, fmaf(c3.z, py, fmaf(c3.w, pz, c3.x)));
            m0 = fminf(m0, v0);
            m1 = fminf(m1, v1);
            m2 = fminf(m2, v2);
            m3 = fminf(m3, v3);
        }
    }

    float m = fminf(fminf(m0, m1), fminf(m2, m3)) + p2;

    // block reduction: sum of per-query mins
    #pragma unroll
    for (int off = 16; off > 0; off >>= 1)
        m += __shfl_down_sync(0xffffffffu, m, off);
    if ((threadIdx.x & 31) == 0)
        wsum[threadIdx.x >> 5] = m;
    __syncthreads();
    if (threadIdx.x == 0) {
        float s = 0.0f;
        #pragma unroll
        for (int w = 0; w < THREADS / 32; w++) s += wsum[w];
        atomicAdd(out, s * (1.0f / (float)(BATCH * NPTS)));
    }
}

extern "C" void kernel_launch(void* const* d_in, const int* in_sizes, int n_in,
                              void* d_out, int out_size)
{
    const float* pred   = (const float*)d_in[0];
    const float* target = (const float*)d_in[1];
    float* out = (float*)d_out;

    zero_kernel<<<1, 32>>>(out);
    chamfer_kernel<<<2 * BATCH * CHUNKS, THREADS>>>(pred, target, out);
}

// round 2
// speedup vs baseline: 1.1855x; 1.1855x over previous
#include <cuda_runtime.h>

#define BATCH   8
#define NPTS    4096
#define THREADS 128
#define CHUNKS  (NPTS / THREADS)   // 32 query chunks per batch
#define SPLIT   2                  // candidate split per query chunk
#define CTILE   (NPTS / SPLIT)     // 2048 candidates per block
#define CPAIRS  (CTILE / 2)        // 1024 packed candidate pairs
#define NQ      (2 * BATCH * NPTS) // 65536 query slots (both directions)

__device__ unsigned g_min[NQ];     // order-preserving float keys

// ---- f32x2 helpers -------------------------------------------------------
__device__ __forceinline__ unsigned long long pk(float lo, float hi) {
    unsigned long long r;
    asm("mov.b64 %0, {%1, %2};" : "=l"(r)
        : "r"(__float_as_uint(lo)), "r"(__float_as_uint(hi)));
    return r;
}
__device__ __forceinline__ unsigned long long fma2(
    unsigned long long a, unsigned long long b, unsigned long long c) {
    unsigned long long d;
    asm("fma.rn.f32x2 %0, %1, %2, %3;" : "=l"(d) : "l"(a), "l"(b), "l"(c));
    return d;
}
__device__ __forceinline__ void unpk(unsigned long long v, float& lo, float& hi) {
    unsigned a, b;
    asm("mov.b64 {%0, %1}, %2;" : "=r"(a), "=r"(b) : "l"(v));
    lo = __uint_as_float(a);
    hi = __uint_as_float(b);
}

// ---- order-preserving float<->uint key -----------------------------------
__device__ __forceinline__ unsigned fkey(float f) {
    unsigned u = __float_as_uint(f);
    return (u >> 31) ? ~u : (u | 0x80000000u);
}
__device__ __forceinline__ float fdecode(unsigned k) {
    unsigned u = (k >> 31) ? (k & 0x7FFFFFFFu) : ~k;
    return __uint_as_float(u);
}

// ---- kernel A: init scratch + output -------------------------------------
__global__ void init_kernel(float* out) {
    int i = blockIdx.x * blockDim.x + threadIdx.x;
    if (i < NQ) g_min[i] = 0xFFFFFFFFu;
    if (i == 0) out[0] = 0.0f;
}

// ---- kernel B: per-(dir,batch,chunk,split) partial min -------------------
__global__ __launch_bounds__(THREADS)
void chamfer_kernel(const float* __restrict__ pred,
                    const float* __restrict__ target)
{
    // packed candidate pairs: sm[2k] = (t2 pair, -2x pair), sm[2k+1] = (-2y, -2z)
    __shared__ ulonglong2 sm[2 * CPAIRS];   // 32 KB

    int bid   = blockIdx.x;
    int s     = bid & (SPLIT - 1);
    int chunk = (bid >> 1) & (CHUNKS - 1);
    int b     = (bid >> 6) & (BATCH - 1);
    int dir   = bid >> 9;

    const float* Q = dir ? target : pred;
    const float* C = dir ? pred   : target;

    // query point for this thread
    int i = chunk * THREADS + threadIdx.x;
    const float* qp = Q + ((size_t)b * NPTS + i) * 3;
    float px = qp[0], py = qp[1], pz = qp[2];
    float p2 = px * px + py * py + pz * pz;
    unsigned long long pxp = pk(px, px), pyp = pk(py, py), pzp = pk(pz, pz);

    // cooperative load + pack of this block's candidate tile (2048 points)
    // pair k covers candidates (2k, 2k+1); 24-byte pair strides are float2-aligned
    const float2* cb2 = (const float2*)(C + ((size_t)b * NPTS + s * CTILE) * 3);
    for (int k = threadIdx.x; k < CPAIRS; k += THREADS) {
        float2 f0 = cb2[3 * k + 0];   // x0 y0
        float2 f1 = cb2[3 * k + 1];   // z0 x1
        float2 f2 = cb2[3 * k + 2];   // y1 z1
        float x0 = f0.x, y0 = f0.y, z0 = f1.x;
        float x1 = f1.y, y1 = f2.x, z1 = f2.y;
        float t20 = x0 * x0 + y0 * y0 + z0 * z0;
        float t21 = x1 * x1 + y1 * y1 + z1 * z1;
        sm[2 * k]     = make_ulonglong2(pk(t20, t21), pk(-2.f * x0, -2.f * x1));
        sm[2 * k + 1] = make_ulonglong2(pk(-2.f * y0, -2.f * y1), pk(-2.f * z0, -2.f * z1));
    }
    __syncthreads();

    float m0 = 3.0e38f, m1 = 3.0e38f, m2 = 3.0e38f, m3 = 3.0e38f;

    #pragma unroll 4
    for (int k = 0; k < CPAIRS; k += 2) {
        ulonglong2 a0 = sm[2 * k + 0];
        ulonglong2 b0 = sm[2 * k + 1];
        ulonglong2 a1 = sm[2 * k + 2];
        ulonglong2 b1 = sm[2 * k + 3];

        unsigned long long v0 = fma2(b0.y, pzp, fma2(b0.x, pyp, fma2(a0.y, pxp, a0.x)));
        unsigned long long v1 = fma2(b1.y, pzp, fma2(b1.x, pyp, fma2(a1.y, pxp, a1.x)));

        float lo, hi;
        unpk(v0, lo, hi);
        m0 = fminf(m0, lo); m1 = fminf(m1, hi);
        unpk(v1, lo, hi);
        m2 = fminf(m2, lo); m3 = fminf(m3, hi);
    }

    float m = fminf(fminf(m0, m1), fminf(m2, m3)) + p2;

    int idx = (dir * BATCH + b) * NPTS + i;
    atomicMin(&g_min[idx], fkey(m));
}

// ---- kernel C: decode + sum + scale --------------------------------------
__global__ void reduce_kernel(float* out) {
    __shared__ float wsum[8];
    int tid  = threadIdx.x;
    int base = blockIdx.x * 1024;   // 64 blocks x 256 threads x 4 values

    float s = 0.0f;
    #pragma unroll
    for (int r = 0; r < 4; r++)
        s += fdecode(g_min[base + r * 256 + tid]);

    #pragma unroll
    for (int off = 16; off > 0; off >>= 1)
        s += __shfl_down_sync(0xffffffffu, s, off);
    if ((tid & 31) == 0) wsum[tid >> 5] = s;
    __syncthreads();
    if (tid == 0) {
        float t = 0.0f;
        #pragma unroll
        for (int w = 0; w < 8; w++) t += wsum[w];
        atomicAdd(out, t * (1.0f / (float)(BATCH * NPTS)));
    }
}

extern "C" void kernel_launch(void* const* d_in, const int* in_sizes, int n_in,
                              void* d_out, int out_size)
{
    const float* pred   = (const float*)d_in[0];
    const float* target = (const float*)d_in[1];
    float* out = (float*)d_out;

    init_kernel<<<(NQ + 255) / 256, 256>>>(out);
    chamfer_kernel<<<2 * BATCH * CHUNKS * SPLIT, THREADS>>>(pred, target);
    reduce_kernel<<<NQ / 1024, 256>>>(out);
}

// round 3
// speedup vs baseline: 1.7255x; 1.4555x over previous
#include <cuda_runtime.h>

#define BATCH   8
#define NPTS    4096
#define THREADS 128
#define QBLK    4                        // queries per thread
#define QCH     (QBLK * THREADS)         // 512 queries per block
#define QCHUNKS (NPTS / QCH)             // 8 query chunks per (dir,batch)
#define SPLIT   8                        // candidate splits
#define CTILE   (NPTS / SPLIT)           // 512 candidates per block
#define CPAIRS  (CTILE / 2)              // 256 packed candidate pairs
#define NQ      (2 * BATCH * NPTS)       // 65536 query slots (both dirs)
#define NBLK    (2 * BATCH * QCHUNKS * SPLIT)  // 1024 chamfer blocks
#define RBLK    (NQ / 256)               // 256 reduce blocks

__device__ float    g_part[SPLIT * NQ];  // [s][query] partial mins, plain stores
__device__ float    g_bsum[RBLK];
__device__ unsigned g_tick;              // zero-initialized; reset by last block

// ---- f32x2 helpers -------------------------------------------------------
__device__ __forceinline__ unsigned long long pk(float lo, float hi) {
    unsigned long long r;
    asm("mov.b64 %0, {%1, %2};" : "=l"(r)
        : "r"(__float_as_uint(lo)), "r"(__float_as_uint(hi)));
    return r;
}
__device__ __forceinline__ unsigned long long fma2(
    unsigned long long a, unsigned long long b, unsigned long long c) {
    unsigned long long d;
    asm("fma.rn.f32x2 %0, %1, %2, %3;" : "=l"(d) : "l"(a), "l"(b), "l"(c));
    return d;
}
__device__ __forceinline__ void unpk(unsigned long long v, float& lo, float& hi) {
    unsigned a, b;
    asm("mov.b64 {%0, %1}, %2;" : "=r"(a), "=r"(b) : "l"(v));
    lo = __uint_as_float(a);
    hi = __uint_as_float(b);
}

// ---- kernel 1: per-(dir,batch,chunk,split) partial mins ------------------
__global__ __launch_bounds__(THREADS)
void chamfer_kernel(const float* __restrict__ pred,
                    const float* __restrict__ target)
{
    // packed candidate pairs: sm[2k]=(t2 pair, -2x pair), sm[2k+1]=(-2y, -2z)
    __shared__ ulonglong2 sm[2 * CPAIRS];   // 8 KB

    int bid   = blockIdx.x;
    int s     = bid & (SPLIT - 1);
    int chunk = (bid >> 3) & (QCHUNKS - 1);
    int b     = (bid >> 6) & (BATCH - 1);
    int dir   = bid >> 9;

    const float* Q = dir ? target : pred;
    const float* C = dir ? pred   : target;

    // 4 query points per thread, stride-THREADS for coalescing
    int qbase = chunk * QCH + threadIdx.x;
    unsigned long long pxp[QBLK], pyp[QBLK], pzp[QBLK];
    float p2[QBLK];
    #pragma unroll
    for (int q = 0; q < QBLK; q++) {
        const float* qp = Q + ((size_t)b * NPTS + qbase + q * THREADS) * 3;
        float px = qp[0], py = qp[1], pz = qp[2];
        p2[q]  = px * px + py * py + pz * pz;
        pxp[q] = pk(px, px);
        pyp[q] = pk(py, py);
        pzp[q] = pk(pz, pz);
    }

    // cooperative load + pack of this block's candidate tile (512 points)
    const float2* cb2 = (const float2*)(C + ((size_t)b * NPTS + s * CTILE) * 3);
    for (int k = threadIdx.x; k < CPAIRS; k += THREADS) {
        float2 f0 = cb2[3 * k + 0];   // x0 y0
        float2 f1 = cb2[3 * k + 1];   // z0 x1
        float2 f2 = cb2[3 * k + 2];   // y1 z1
        float x0 = f0.x, y0 = f0.y, z0 = f1.x;
        float x1 = f1.y, y1 = f2.x, z1 = f2.y;
        float t20 = x0 * x0 + y0 * y0 + z0 * z0;
        float t21 = x1 * x1 + y1 * y1 + z1 * z1;
        sm[2 * k]     = make_ulonglong2(pk(t20, t21), pk(-2.f * x0, -2.f * x1));
        sm[2 * k + 1] = make_ulonglong2(pk(-2.f * y0, -2.f * y1), pk(-2.f * z0, -2.f * z1));
    }
    __syncthreads();

    float mlo[QBLK], mhi[QBLK];
    #pragma unroll
    for (int q = 0; q < QBLK; q++) { mlo[q] = 3.0e38f; mhi[q] = 3.0e38f; }

    #pragma unroll 2
    for (int k = 0; k < CPAIRS; k += 2) {
        ulonglong2 a0 = sm[2 * k + 0];
        ulonglong2 b0 = sm[2 * k + 1];
        ulonglong2 a1 = sm[2 * k + 2];
        ulonglong2 b1 = sm[2 * k + 3];
        #pragma unroll
        for (int q = 0; q < QBLK; q++) {
            unsigned long long v0 =
                fma2(b0.y, pzp[q], fma2(b0.x, pyp[q], fma2(a0.y, pxp[q], a0.x)));
            unsigned long long v1 =
                fma2(b1.y, pzp[q], fma2(b1.x, pyp[q], fma2(a1.y, pxp[q], a1.x)));
            float lo, hi;
            unpk(v0, lo, hi);
            mlo[q] = fminf(mlo[q], lo);
            mhi[q] = fminf(mhi[q], hi);
            unpk(v1, lo, hi);
            mlo[q] = fminf(mlo[q], lo);
            mhi[q] = fminf(mhi[q], hi);
        }
    }

    // coalesced plain stores of partial mins (no init, no atomics)
    int qidx = (dir * BATCH + b) * NPTS + qbase;
    #pragma unroll
    for (int q = 0; q < QBLK; q++)
        g_part[s * NQ + qidx + q * THREADS] =
            fminf(mlo[q], mhi[q]) + p2[q];
}

// ---- kernel 2: min over splits, sum, ticket-counter finish ---------------
__global__ __launch_bounds__(256)
void reduce_kernel(float* __restrict__ out)
{
    __shared__ float wsum[8];
    __shared__ int   is_last;
    int tid = threadIdx.x;
    int qi  = blockIdx.x * 256 + tid;

    float m = 3.0e38f;
    #pragma unroll
    for (int s = 0; s < SPLIT; s++)
        m = fminf(m, g_part[s * NQ + qi]);

    #pragma unroll
    for (int off = 16; off > 0; off >>= 1)
        m += __shfl_down_sync(0xffffffffu, m, off);
    if ((tid & 31) == 0) wsum[tid >> 5] = m;
    __syncthreads();

    if (tid == 0) {
        float s = 0.0f;
        #pragma unroll
        for (int w = 0; w < 8; w++) s += wsum[w];
        g_bsum[blockIdx.x] = s;
        __threadfence();
        unsigned t = atomicAdd(&g_tick, 1u);
        is_last = (t == RBLK - 1);
    }
    __syncthreads();

    if (is_last && tid < 32) {
        __threadfence();
        float s = 0.0f;
        #pragma unroll
        for (int r = 0; r < RBLK / 32; r++)
            s += *((volatile float*)&g_bsum[r * 32 + tid]);
        #pragma unroll
        for (int off = 16; off > 0; off >>= 1)
            s += __shfl_down_sync(0xffffffffu, s, off);
        if (tid == 0) {
            out[0] = s * (1.0f / (float)(BATCH * NPTS));
            g_tick = 0;   // self-reset for next graph replay
        }
    }
}

extern "C" void kernel_launch(void* const* d_in, const int* in_sizes, int n_in,
                              void* d_out, int out_size)
{
    const float* pred   = (const float*)d_in[0];
    const float* target = (const float*)d_in[1];
    float* out = (float*)d_out;

    chamfer_kernel<<<NBLK, THREADS>>>(pred, target);
    reduce_kernel<<<RBLK, 256>>>(out);
}

// round 4
// speedup vs baseline: 1.9551x; 1.1331x over previous
#include <cuda_runtime.h>

#define BATCH   8
#define NPTS    4096
#define THREADS 128
#define QBLK    4                        // queries per thread
#define QCH     (QBLK * THREADS)         // 512 queries per block
#define QCHUNKS (NPTS / QCH)             // 8 query chunks per (dir,batch)
#define SPLIT   8                        // candidate splits
#define CTILE   (NPTS / SPLIT)           // 512 candidates per block
#define CPAIRS  (CTILE / 2)              // 256 packed candidate pairs
#define NQ      (2 * BATCH * NPTS)       // 65536 query slots (both dirs)
#define NBLK    (2 * BATCH * QCHUNKS * SPLIT)  // 1024 chamfer blocks
#define RBLK    64                       // reduce blocks (256 thr x 4 queries)

__device__ float    g_part[SPLIT * NQ];  // [s][query] partial mins
__device__ float    g_bsum[RBLK];
__device__ unsigned g_tick;              // zero-init; self-reset each replay

// ---- f32x2 helpers -------------------------------------------------------
__device__ __forceinline__ unsigned long long pk(float lo, float hi) {
    unsigned long long r;
    asm("mov.b64 %0, {%1, %2};" : "=l"(r)
        : "r"(__float_as_uint(lo)), "r"(__float_as_uint(hi)));
    return r;
}
__device__ __forceinline__ unsigned long long fma2(
    unsigned long long a, unsigned long long b, unsigned long long c) {
    unsigned long long d;
    asm("fma.rn.f32x2 %0, %1, %2, %3;" : "=l"(d) : "l"(a), "l"(b), "l"(c));
    return d;
}
__device__ __forceinline__ void unpk(unsigned long long v, float& lo, float& hi) {
    unsigned a, b;
    asm("mov.b64 {%0, %1}, %2;" : "=r"(a), "=r"(b) : "l"(v));
    lo = __uint_as_float(a);
    hi = __uint_as_float(b);
}

// ---- kernel 1: per-(dir,batch,chunk,split) partial mins ------------------
__global__ __launch_bounds__(THREADS, 8)
void chamfer_kernel(const float* __restrict__ pred,
                    const float* __restrict__ target)
{
    // packed candidate pairs: sm[2k]=(t2 pair, -2x pair), sm[2k+1]=(-2y, -2z)
    __shared__ ulonglong2 sm[2 * CPAIRS];   // 8 KB

    int bid   = blockIdx.x;
    int s     = bid & (SPLIT - 1);
    int chunk = (bid >> 3) & (QCHUNKS - 1);
    int b     = (bid >> 6) & (BATCH - 1);
    int dir   = bid >> 9;

    const float* Q = dir ? target : pred;
    const float* C = dir ? pred   : target;

    // 4 query points per thread, stride-THREADS for coalescing
    int qbase = chunk * QCH + threadIdx.x;
    unsigned long long pxp[QBLK], pyp[QBLK], pzp[QBLK];
    float p2[QBLK];
    #pragma unroll
    for (int q = 0; q < QBLK; q++) {
        const float* qp = Q + ((size_t)b * NPTS + qbase + q * THREADS) * 3;
        float px = qp[0], py = qp[1], pz = qp[2];
        p2[q]  = px * px + py * py + pz * pz;
        pxp[q] = pk(px, px);
        pyp[q] = pk(py, py);
        pzp[q] = pk(pz, pz);
    }

    // cooperative load + pack of this block's candidate tile (512 points)
    const float2* cb2 = (const float2*)(C + ((size_t)b * NPTS + s * CTILE) * 3);
    for (int k = threadIdx.x; k < CPAIRS; k += THREADS) {
        float2 f0 = cb2[3 * k + 0];   // x0 y0
        float2 f1 = cb2[3 * k + 1];   // z0 x1
        float2 f2 = cb2[3 * k + 2];   // y1 z1
        float x0 = f0.x, y0 = f0.y, z0 = f1.x;
        float x1 = f1.y, y1 = f2.x, z1 = f2.y;
        float t20 = x0 * x0 + y0 * y0 + z0 * z0;
        float t21 = x1 * x1 + y1 * y1 + z1 * z1;
        sm[2 * k]     = make_ulonglong2(pk(t20, t21), pk(-2.f * x0, -2.f * x1));
        sm[2 * k + 1] = make_ulonglong2(pk(-2.f * y0, -2.f * y1), pk(-2.f * z0, -2.f * z1));
    }
    __syncthreads();

    float mlo[QBLK], mhi[QBLK];
    #pragma unroll
    for (int q = 0; q < QBLK; q++) { mlo[q] = 3.0e38f; mhi[q] = 3.0e38f; }

    #pragma unroll 2
    for (int k = 0; k < CPAIRS; k += 2) {
        ulonglong2 a0 = sm[2 * k + 0];
        ulonglong2 b0 = sm[2 * k + 1];
        ulonglong2 a1 = sm[2 * k + 2];
        ulonglong2 b1 = sm[2 * k + 3];
        #pragma unroll
        for (int q = 0; q < QBLK; q++) {
            unsigned long long v0 =
                fma2(b0.y, pzp[q], fma2(b0.x, pyp[q], fma2(a0.y, pxp[q], a0.x)));
            unsigned long long v1 =
                fma2(b1.y, pzp[q], fma2(b1.x, pyp[q], fma2(a1.y, pxp[q], a1.x)));
            float lo0, hi0, lo1, hi1;
            unpk(v0, lo0, hi0);
            unpk(v1, lo1, hi1);
            // tournament: halves the loop-carried FMNMX chain on mlo/mhi
            mlo[q] = fminf(mlo[q], fminf(lo0, lo1));
            mhi[q] = fminf(mhi[q], fminf(hi0, hi1));
        }
    }

    // coalesced plain stores of partial mins (no init, no atomics)
    int qidx = (dir * BATCH + b) * NPTS + qbase;
    #pragma unroll
    for (int q = 0; q < QBLK; q++)
        g_part[s * NQ + qidx + q * THREADS] =
            fminf(mlo[q], mhi[q]) + p2[q];
}

// ---- kernel 2: min over splits, sum, ticket-counter finish ---------------
__global__ __launch_bounds__(256)
void reduce_kernel(float* __restrict__ out)
{
    __shared__ float wsum[8];
    __shared__ int   is_last;
    int tid = threadIdx.x;
    int q4  = (blockIdx.x * 256 + tid) * 4;   // 4 contiguous queries

    float4 m = make_float4(3.0e38f, 3.0e38f, 3.0e38f, 3.0e38f);
    #pragma unroll
    for (int s = 0; s < SPLIT; s++) {
        float4 v = *(const float4*)&g_part[s * NQ + q4];
        m.x = fminf(m.x, v.x);
        m.y = fminf(m.y, v.y);
        m.z = fminf(m.z, v.z);
        m.w = fminf(m.w, v.w);
    }
    float sum = (m.x + m.y) + (m.z + m.w);

    #pragma unroll
    for (int off = 16; off > 0; off >>= 1)
        sum += __shfl_down_sync(0xffffffffu, sum, off);
    if ((tid & 31) == 0) wsum[tid >> 5] = sum;
    __syncthreads();

    if (tid == 0) {
        float s = 0.0f;
        #pragma unroll
        for (int w = 0; w < 8; w++) s += wsum[w];
        g_bsum[blockIdx.x] = s;
        __threadfence();
        unsigned t = atomicAdd(&g_tick, 1u);
        is_last = (t == RBLK - 1);
    }
    __syncthreads();

    if (is_last && tid < 32) {
        __threadfence();
        float s = 0.0f;
        #pragma unroll
        for (int r = 0; r < RBLK / 32; r++)
            s += *((volatile float*)&g_bsum[r * 32 + tid]);
        #pragma unroll
        for (int off = 16; off > 0; off >>= 1)
            s += __shfl_down_sync(0xffffffffu, s, off);
        if (tid == 0) {
            out[0] = s * (1.0f / (float)(BATCH * NPTS));
            g_tick = 0;   // self-reset for next graph replay
        }
    }
}

extern "C" void kernel_launch(void* const* d_in, const int* in_sizes, int n_in,
                              void* d_out, int out_size)
{
    const float* pred   = (const float*)d_in[0];
    const float* target = (const float*)d_in[1];
    float* out = (float*)d_out;

    chamfer_kernel<<<NBLK, THREADS>>>(pred, target);
    reduce_kernel<<<RBLK, 256>>>(out);
}

// round 5
// speedup vs baseline: 1.9888x; 1.0172x over previous
#include <cuda_runtime.h>

#define BATCH   8
#define NPTS    4096
#define THREADS 128
#define QBLK    8                        // queries per thread
#define QCH     (QBLK * THREADS)         // 1024 queries per block
#define QCHUNKS (NPTS / QCH)             // 4 query chunks per (dir,batch)
#define SPLIT   16                       // candidate splits
#define CTILE   (NPTS / SPLIT)           // 256 candidates per block
#define CPAIRS  (CTILE / 2)              // 128 packed candidate pairs
#define NQ      (2 * BATCH * NPTS)       // 65536 query slots (both dirs)
#define NBLK    (2 * BATCH * QCHUNKS * SPLIT)  // 1024 chamfer blocks
#define RBLK    64                       // reduce blocks

__device__ unsigned g_max[NQ];   // reversed order keys; 0 == +inf identity
__device__ float    g_bsum[RBLK];
__device__ unsigned g_tick;      // zero-init; self-reset each replay

// ---- f32x2 helpers -------------------------------------------------------
__device__ __forceinline__ unsigned long long pk(float lo, float hi) {
    unsigned long long r;
    asm("mov.b64 %0, {%1, %2};" : "=l"(r)
        : "r"(__float_as_uint(lo)), "r"(__float_as_uint(hi)));
    return r;
}
__device__ __forceinline__ unsigned long long fma2(
    unsigned long long a, unsigned long long b, unsigned long long c) {
    unsigned long long d;
    asm("fma.rn.f32x2 %0, %1, %2, %3;" : "=l"(d) : "l"(a), "l"(b), "l"(c));
    return d;
}
__device__ __forceinline__ void unpk(unsigned long long v, float& lo, float& hi) {
    unsigned a, b;
    asm("mov.b64 {%0, %1}, %2;" : "=r"(a), "=r"(b) : "l"(v));
    lo = __uint_as_float(a);
    hi = __uint_as_float(b);
}

// order-preserving float->uint key, REVERSED (smaller float -> larger key)
// so zero-initialized g_max is the identity for atomicMax (all real keys > 0)
__device__ __forceinline__ unsigned rkey(float f) {
    unsigned u = __float_as_uint(f);
    unsigned k = (u >> 31) ? ~u : (u | 0x80000000u);
    return ~k;
}
__device__ __forceinline__ float rdecode(unsigned r) {
    unsigned k = ~r;
    unsigned u = (k >> 31) ? (k & 0x7FFFFFFFu) : ~k;
    return __uint_as_float(u);
}

// ---- kernel 1: per-(dir,batch,chunk,split) partial mins ------------------
__global__ __launch_bounds__(THREADS, 4)
void chamfer_kernel(const float* __restrict__ pred,
                    const float* __restrict__ target)
{
    // packed candidate pairs: sm[2k]=(t2 pair, -2x pair), sm[2k+1]=(-2y, -2z)
    __shared__ ulonglong2 sm[2 * CPAIRS];   // 4 KB

    int bid   = blockIdx.x;
    int s     = bid & (SPLIT - 1);
    int chunk = (bid >> 4) & (QCHUNKS - 1);
    int b     = (bid >> 6) & (BATCH - 1);
    int dir   = bid >> 9;

    const float* Q = dir ? target : pred;
    const float* C = dir ? pred   : target;

    // 8 query points per thread, stride-THREADS for coalescing
    int qbase = chunk * QCH + threadIdx.x;
    unsigned long long pxp[QBLK], pyp[QBLK], pzp[QBLK];
    float p2[QBLK];
    #pragma unroll
    for (int q = 0; q < QBLK; q++) {
        const float* qp = Q + ((size_t)b * NPTS + qbase + q * THREADS) * 3;
        float px = qp[0], py = qp[1], pz = qp[2];
        p2[q]  = px * px + py * py + pz * pz;
        pxp[q] = pk(px, px);
        pyp[q] = pk(py, py);
        pzp[q] = pk(pz, pz);
    }

    // cooperative load + pack of this block's candidate tile (256 points)
    const float2* cb2 = (const float2*)(C + ((size_t)b * NPTS + s * CTILE) * 3);
    for (int k = threadIdx.x; k < CPAIRS; k += THREADS) {
        float2 f0 = cb2[3 * k + 0];   // x0 y0
        float2 f1 = cb2[3 * k + 1];   // z0 x1
        float2 f2 = cb2[3 * k + 2];   // y1 z1
        float x0 = f0.x, y0 = f0.y, z0 = f1.x;
        float x1 = f1.y, y1 = f2.x, z1 = f2.y;
        float t20 = x0 * x0 + y0 * y0 + z0 * z0;
        float t21 = x1 * x1 + y1 * y1 + z1 * z1;
        sm[2 * k]     = make_ulonglong2(pk(t20, t21), pk(-2.f * x0, -2.f * x1));
        sm[2 * k + 1] = make_ulonglong2(pk(-2.f * y0, -2.f * y1), pk(-2.f * z0, -2.f * z1));
    }
    __syncthreads();

    float mlo[QBLK], mhi[QBLK];
    #pragma unroll
    for (int q = 0; q < QBLK; q++) { mlo[q] = 3.0e38f; mhi[q] = 3.0e38f; }

    #pragma unroll 2
    for (int k = 0; k < CPAIRS; k += 2) {
        ulonglong2 a0 = sm[2 * k + 0];
        ulonglong2 b0 = sm[2 * k + 1];
        ulonglong2 a1 = sm[2 * k + 2];
        ulonglong2 b1 = sm[2 * k + 3];
        #pragma unroll
        for (int q = 0; q < QBLK; q++) {
            unsigned long long v0 =
                fma2(b0.y, pzp[q], fma2(b0.x, pyp[q], fma2(a0.y, pxp[q], a0.x)));
            unsigned long long v1 =
                fma2(b1.y, pzp[q], fma2(b1.x, pyp[q], fma2(a1.y, pxp[q], a1.x)));
            float lo0, hi0, lo1, hi1;
            unpk(v0, lo0, hi0);
            unpk(v1, lo1, hi1);
            mlo[q] = fminf(mlo[q], fminf(lo0, lo1));
            mhi[q] = fminf(mhi[q], fminf(hi0, hi1));
        }
    }

    // fold into per-query global min (0 is the atomicMax identity -> no init)
    int qidx = (dir * BATCH + b) * NPTS + qbase;
    #pragma unroll
    for (int q = 0; q < QBLK; q++) {
        float m = fminf(mlo[q], mhi[q]) + p2[q];
        atomicMax(&g_max[qidx + q * THREADS], rkey(m));
    }
}

// ---- kernel 2: decode + sum + self-reset + ticket finish -----------------
__global__ __launch_bounds__(256)
void reduce_kernel(float* __restrict__ out)
{
    __shared__ float wsum[8];
    __shared__ int   is_last;
    int tid = threadIdx.x;
    int i4  = (blockIdx.x * 256 + tid) * 4;   // 4 contiguous keys

    uint4 k = *(const uint4*)&g_max[i4];
    // reset for next graph replay
    *(uint4*)&g_max[i4] = make_uint4(0u, 0u, 0u, 0u);

    float sum = (rdecode(k.x) + rdecode(k.y)) + (rdecode(k.z) + rdecode(k.w));

    #pragma unroll
    for (int off = 16; off > 0; off >>= 1)
        sum += __shfl_down_sync(0xffffffffu, sum, off);
    if ((tid & 31) == 0) wsum[tid >> 5] = sum;
    __syncthreads();

    if (tid == 0) {
        float s = 0.0f;
        #pragma unroll
        for (int w = 0; w < 8; w++) s += wsum[w];
        g_bsum[blockIdx.x] = s;
        __threadfence();
        unsigned t = atomicAdd(&g_tick, 1u);
        is_last = (t == RBLK - 1);
    }
    __syncthreads();

    if (is_last && tid < 32) {
        __threadfence();
        float s = 0.0f;
        #pragma unroll
        for (int r = 0; r < RBLK / 32; r++)
            s += *((volatile float*)&g_bsum[r * 32 + tid]);
        #pragma unroll
        for (int off = 16; off > 0; off >>= 1)
            s += __shfl_down_sync(0xffffffffu, s, off);
        if (tid == 0) {
            out[0] = s * (1.0f / (float)(BATCH * NPTS));
            g_tick = 0;   // self-reset for next graph replay
        }
    }
}

extern "C" void kernel_launch(void* const* d_in, const int* in_sizes, int n_in,
                              void* d_out, int out_size)
{
    const float* pred   = (const float*)d_in[0];
    const float* target = (const float*)d_in[1];
    float* out = (float*)d_out;

    chamfer_kernel<<<NBLK, THREADS>>>(pred, target);
    reduce_kernel<<<RBLK, 256>>>(out);
}